// round 1
// baseline (speedup 1.0000x reference)
#include <cuda_runtime.h>
#include <math.h>

// ---------------- scratch (device globals; no allocation) ----------------
__device__ float g_h1[512*8*32*32];      // 16 MB  conv1 pooled out [b][oc][32][32]
__device__ float g_h2[512*16*16*16];     //  8 MB  conv2 pooled out [b][oc][16][16]
__device__ float g_feats[512*64*32];     //  4 MB  feats [b][r=64][c=32]
__device__ float g_uhat[512*64*256];     // 33.5 MB u_hat [b][r][no=n*8+o]
__device__ float g_v1[512*256];          //  0.5 MB v1 [b][n=32][o=8]

// ---------------- conv1: [512,3,64,64] -> relu -> pool -> g_h1 ----------------
__global__ __launch_bounds__(256) void conv1_k(const float* __restrict__ x,
                                               const float* __restrict__ w,
                                               const float* __restrict__ bias) {
    __shared__ float ws[216];
    __shared__ float bs[8];
    int tid = threadIdx.x;
    if (tid < 216) ws[tid] = w[tid];
    if (tid < 8)   bs[tid] = bias[tid];
    __syncthreads();

    int b   = blockIdx.x >> 2;
    int pos = ((blockIdx.x & 3) << 8) + tid;   // 0..1023
    int ph = pos >> 5, pw = pos & 31;
    int y0 = 2*ph - 1, x0 = 2*pw - 1;

    float win[3][4][4];
#pragma unroll
    for (int c = 0; c < 3; c++) {
#pragma unroll
        for (int yy = 0; yy < 4; yy++) {
            int y = y0 + yy;
            bool yok = (y >= 0 && y < 64);
            const float* row = x + ((b*3 + c)*64 + y)*64;
#pragma unroll
            for (int xx = 0; xx < 4; xx++) {
                int xp = x0 + xx;
                win[c][yy][xx] = (yok && xp >= 0 && xp < 64) ? row[xp] : 0.f;
            }
        }
    }

#pragma unroll 1
    for (int oc = 0; oc < 8; oc++) {
        float a00 = bs[oc], a01 = a00, a10 = a00, a11 = a00;
        const float* wp = ws + oc*27;
#pragma unroll
        for (int c = 0; c < 3; c++)
#pragma unroll
            for (int ky = 0; ky < 3; ky++)
#pragma unroll
                for (int kx = 0; kx < 3; kx++) {
                    float wv = wp[c*9 + ky*3 + kx];
                    a00 += win[c][ky  ][kx  ]*wv;
                    a01 += win[c][ky  ][kx+1]*wv;
                    a10 += win[c][ky+1][kx  ]*wv;
                    a11 += win[c][ky+1][kx+1]*wv;
                }
        float m = fmaxf(fmaxf(fmaxf(a00,a01), fmaxf(a10,a11)), 0.f);
        g_h1[((b*8 + oc)*32 + ph)*32 + pw] = m;
    }
}

// ---------------- conv2: g_h1 -> relu -> pool -> g_h2 ----------------
__global__ __launch_bounds__(256) void conv2_k(const float* __restrict__ w,
                                               const float* __restrict__ bias) {
    __shared__ float hs[8192];     // 8*32*32
    __shared__ float ws[1152];     // 16*8*9
    __shared__ float bs[16];
    int tid = threadIdx.x, b = blockIdx.x;
    for (int i = tid; i < 8192; i += 256) hs[i] = g_h1[b*8192 + i];
    for (int i = tid; i < 1152; i += 256) ws[i] = w[i];
    if (tid < 16) bs[tid] = bias[tid];
    __syncthreads();

    int ph = tid >> 4, pw = tid & 15;
    int y0 = 2*ph - 1, x0 = 2*pw - 1;

    float acc[16][4];
#pragma unroll
    for (int oc = 0; oc < 16; oc++) {
        float bb = bs[oc];
        acc[oc][0]=bb; acc[oc][1]=bb; acc[oc][2]=bb; acc[oc][3]=bb;
    }

#pragma unroll 1
    for (int ic = 0; ic < 8; ic++) {
        float win[4][4];
#pragma unroll
        for (int yy = 0; yy < 4; yy++) {
            int y = y0 + yy;
            bool yok = (y >= 0 && y < 32);
#pragma unroll
            for (int xx = 0; xx < 4; xx++) {
                int xp = x0 + xx;
                win[yy][xx] = (yok && xp >= 0 && xp < 32) ? hs[ic*1024 + y*32 + xp] : 0.f;
            }
        }
#pragma unroll
        for (int oc = 0; oc < 16; oc++) {
            const float* wp = ws + (oc*8 + ic)*9;
#pragma unroll
            for (int ky = 0; ky < 3; ky++)
#pragma unroll
                for (int kx = 0; kx < 3; kx++) {
                    float wv = wp[ky*3 + kx];
                    acc[oc][0] += win[ky  ][kx  ]*wv;
                    acc[oc][1] += win[ky  ][kx+1]*wv;
                    acc[oc][2] += win[ky+1][kx  ]*wv;
                    acc[oc][3] += win[ky+1][kx+1]*wv;
                }
        }
    }
#pragma unroll
    for (int oc = 0; oc < 16; oc++) {
        float m = fmaxf(fmaxf(fmaxf(acc[oc][0],acc[oc][1]), fmaxf(acc[oc][2],acc[oc][3])), 0.f);
        g_h2[((b*16 + oc)*16 + ph)*16 + pw] = m;
    }
}

// ---------------- conv3: g_h2 -> relu -> pool -> g_feats[b][r][c] ----------------
__global__ __launch_bounds__(256) void conv3_k(const float* __restrict__ w,
                                               const float* __restrict__ bias) {
    __shared__ float hs[4096];     // 16*16*16
    __shared__ float ws[4608];     // 32*16*9
    __shared__ float bs[32];
    int tid = threadIdx.x, b = blockIdx.x;
    for (int i = tid; i < 4096; i += 256) hs[i] = g_h2[b*4096 + i];
    for (int i = tid; i < 4608; i += 256) ws[i] = w[i];
    if (tid < 32) bs[tid] = bias[tid];
    __syncthreads();

    int pos = tid & 63;          // spatial r in 8x8
    int ocg = tid >> 6;          // group of 8 output channels
    int ph = pos >> 3, pw = pos & 7;
    int y0 = 2*ph - 1, x0 = 2*pw - 1;

    float acc[8][4];
#pragma unroll
    for (int j = 0; j < 8; j++) {
        float bb = bs[ocg*8 + j];
        acc[j][0]=bb; acc[j][1]=bb; acc[j][2]=bb; acc[j][3]=bb;
    }

#pragma unroll 1
    for (int ic = 0; ic < 16; ic++) {
        float win[4][4];
#pragma unroll
        for (int yy = 0; yy < 4; yy++) {
            int y = y0 + yy;
            bool yok = (y >= 0 && y < 16);
#pragma unroll
            for (int xx = 0; xx < 4; xx++) {
                int xp = x0 + xx;
                win[yy][xx] = (yok && xp >= 0 && xp < 16) ? hs[ic*256 + y*16 + xp] : 0.f;
            }
        }
#pragma unroll
        for (int j = 0; j < 8; j++) {
            const float* wp = ws + ((ocg*8 + j)*16 + ic)*9;
#pragma unroll
            for (int ky = 0; ky < 3; ky++)
#pragma unroll
                for (int kx = 0; kx < 3; kx++) {
                    float wv = wp[ky*3 + kx];
                    acc[j][0] += win[ky  ][kx  ]*wv;
                    acc[j][1] += win[ky  ][kx+1]*wv;
                    acc[j][2] += win[ky+1][kx  ]*wv;
                    acc[j][3] += win[ky+1][kx+1]*wv;
                }
        }
    }
    // feats[b][r=pos][c=ocg*8+j]  (transposed write; r comes from NCHW spatial)
#pragma unroll
    for (int j = 0; j < 8; j++) {
        float m = fmaxf(fmaxf(fmaxf(acc[j][0],acc[j][1]), fmaxf(acc[j][2],acc[j][3])), 0.f);
        g_feats[(b*64 + pos)*32 + ocg*8 + j] = m;
    }
}

// ---------------- u_hat1: per-(r, 64-b tile) GEMM  [64b x 32c] @ [32c x 256no] ----------------
__global__ __launch_bounds__(256) void uhat1_k(const float* __restrict__ rw1) {
    __shared__ float Wr[8192];   // [c=32][no=256]
    __shared__ float fe[2048];   // [b_local=64][c=32]
    int tid = threadIdx.x;
    int r     = blockIdx.x >> 3;
    int bbase = (blockIdx.x & 7) * 64;

    // Wr[c*256 + n*8+o] = rw1[((n*64+r)*32 + c)*8 + o]; tid = c*8+o over (c,o)
    {
        int c = tid >> 3, o = tid & 7;
#pragma unroll 1
        for (int n = 0; n < 32; n++)
            Wr[c*256 + n*8 + o] = rw1[(n*64 + r)*256 + tid];
    }
#pragma unroll
    for (int k = 0; k < 8; k++) {
        int idx = tid + k*256;
        int bb = idx >> 5, c = idx & 31;
        fe[idx] = g_feats[((bbase + bb)*64 + r)*32 + c];
    }
    __syncthreads();

    int wid = tid >> 5, l = tid & 31;  // warp -> 8-b group, lane -> no base
    float acc[8][8];
#pragma unroll
    for (int j = 0; j < 8; j++)
#pragma unroll
        for (int k = 0; k < 8; k++) acc[j][k] = 0.f;

#pragma unroll 2
    for (int c = 0; c < 32; c++) {
        float f[8], wv[8];
#pragma unroll
        for (int j = 0; j < 8; j++) f[j] = fe[(wid*8 + j)*32 + c];
#pragma unroll
        for (int k = 0; k < 8; k++) wv[k] = Wr[c*256 + l + k*32];
#pragma unroll
        for (int j = 0; j < 8; j++)
#pragma unroll
            for (int k = 0; k < 8; k++) acc[j][k] += f[j]*wv[k];
    }

#pragma unroll
    for (int j = 0; j < 8; j++) {
        int base = ((bbase + wid*8 + j)*64 + r)*256;
#pragma unroll
        for (int k = 0; k < 8; k++) g_uhat[base + l + k*32] = acc[j][k];
    }
}

// ---------------- routing1: block per (b, n-half of 16) ----------------
__global__ __launch_bounds__(256) void route1_k() {
    __shared__ float uh[64*129];   // [r][no_local(128)] padded stride 129
    __shared__ float bij[1024];    // [n_local=16][r=64]
    __shared__ float cc[1024];
    __shared__ float sv[128];
    __shared__ float vv[128];
    int tid = threadIdx.x;
    int b  = blockIdx.x >> 1;
    int ng = blockIdx.x & 1;
    const float* src = g_uhat + b*16384 + ng*128;

#pragma unroll
    for (int k = 0; k < 32; k++) {      // 8192 elems
        int i = tid + k*256;
        int r = i >> 7, j = i & 127;
        uh[r*129 + j] = src[r*256 + j];
    }
#pragma unroll
    for (int k = 0; k < 4; k++) bij[tid + k*256] = 0.f;
    __syncthreads();

    for (int it = 0; it < 3; it++) {
        if (it == 0) {
#pragma unroll
            for (int k = 0; k < 4; k++) cc[tid + k*256] = 1.f/64.f;
        } else if (tid < 16) {
            int n = tid;
            float m = -1e30f;
            for (int r = 0; r < 64; r++) m = fmaxf(m, bij[n*64 + r]);
            float s = 0.f;
            for (int r = 0; r < 64; r++) { float e = expf(bij[n*64+r] - m); cc[n*64+r] = e; s += e; }
            float inv = 1.f/s;
            for (int r = 0; r < 64; r++) cc[n*64+r] *= inv;
        }
        __syncthreads();

        if (tid < 128) {                   // s_j: (n_local, o)
            int n = tid >> 3;
            float a = 0.f;
#pragma unroll 4
            for (int r = 0; r < 64; r++) a += cc[n*64 + r]*uh[r*129 + tid];
            sv[tid] = a;
        }
        __syncthreads();
        if (tid < 128) {                   // squash
            int n = tid >> 3;
            float norm = 0.f;
#pragma unroll
            for (int o = 0; o < 8; o++) { float t = sv[n*8 + o]; norm += t*t; }
            float scale = norm/((1.f + norm)*sqrtf(norm + 1e-9f));
            vv[tid] = scale*sv[tid];
        }
        __syncthreads();
        if (it < 2) {                      // b update
#pragma unroll
            for (int k = 0; k < 4; k++) {
                int e = tid + k*256;
                int n = e >> 6, r = e & 63;
                float d = 0.f;
#pragma unroll
                for (int o = 0; o < 8; o++) d += uh[r*129 + n*8 + o]*vv[n*8 + o];
                bij[e] += d;
            }
            __syncthreads();
        }
    }
    if (tid < 128) g_v1[b*256 + ng*128 + tid] = vv[tid];
}

// ---------------- routing2 + FC: block per b ----------------
__global__ __launch_bounds__(256) void route2_k(const float* __restrict__ rw2,
                                                const float* __restrict__ fcw,
                                                const float* __restrict__ fcb,
                                                float* __restrict__ out) {
    __shared__ float fe[256];        // v1[b]: [r=32][c=8]
    __shared__ float u2[15*32*17];   // [n][r][o] padded stride 17
    __shared__ float bij[480];
    __shared__ float cc[480];
    __shared__ float sv[240];
    __shared__ float vv[240];
    int tid = threadIdx.x, b = blockIdx.x;
    fe[tid] = g_v1[b*256 + tid];
    for (int i = tid; i < 480; i += 256) bij[i] = 0.f;
    __syncthreads();

    // u2[n][r][o] = sum_c fe[r][c]*rw2[n][r][c][o]
#pragma unroll 1
    for (int k = 0; k < 30; k++) {
        int e = tid + k*256;                 // e = (n*32+r)*16 + o
        int n = e >> 9, r = (e >> 4) & 31, o = e & 15;
        const float* wp = rw2 + (n*32 + r)*128 + o;
        float a = 0.f;
#pragma unroll
        for (int c = 0; c < 8; c++) a += fe[r*8 + c]*wp[c*16];
        u2[(n*32 + r)*17 + o] = a;
    }
    __syncthreads();

    for (int it = 0; it < 3; it++) {
        if (it == 0) {
            for (int i = tid; i < 480; i += 256) cc[i] = 1.f/32.f;
        } else if (tid < 15) {
            int n = tid;
            float m = -1e30f;
            for (int r = 0; r < 32; r++) m = fmaxf(m, bij[n*32 + r]);
            float s = 0.f;
            for (int r = 0; r < 32; r++) { float e = expf(bij[n*32+r] - m); cc[n*32+r] = e; s += e; }
            float inv = 1.f/s;
            for (int r = 0; r < 32; r++) cc[n*32+r] *= inv;
        }
        __syncthreads();

        if (tid < 240) {                 // s_j: (n, o)
            int n = tid >> 4, o = tid & 15;
            float a = 0.f;
#pragma unroll 4
            for (int r = 0; r < 32; r++) a += cc[n*32 + r]*u2[(n*32 + r)*17 + o];
            sv[tid] = a;
        }
        __syncthreads();
        if (tid < 240) {                 // squash
            int n = tid >> 4;
            float norm = 0.f;
#pragma unroll
            for (int o = 0; o < 16; o++) { float t = sv[n*16 + o]; norm += t*t; }
            float scale = norm/((1.f + norm)*sqrtf(norm + 1e-9f));
            vv[tid] = scale*sv[tid];
        }
        __syncthreads();
        if (it < 2) {
            for (int i = tid; i < 480; i += 256) {
                int n = i >> 5, r = i & 31;
                float d = 0.f;
#pragma unroll
                for (int o = 0; o < 16; o++) d += u2[(n*32 + r)*17 + o]*vv[n*16 + o];
                bij[i] += d;
            }
            __syncthreads();
        }
    }

    // FC: out[b][k] = fcb[k] + sum_j vv[j]*fcw[k*240 + j]
    if (tid < 15) {
        float a = fcb[tid];
        const float* wp = fcw + tid*240;
#pragma unroll 8
        for (int j = 0; j < 240; j++) a += vv[j]*wp[j];
        out[b*15 + tid] = a;
    }
}

// ---------------- launch ----------------
extern "C" void kernel_launch(void* const* d_in, const int* in_sizes, int n_in,
                              void* d_out, int out_size) {
    const float* x   = (const float*)d_in[0];
    const float* w1  = (const float*)d_in[1];
    const float* b1  = (const float*)d_in[2];
    const float* w2  = (const float*)d_in[3];
    const float* b2  = (const float*)d_in[4];
    const float* w3  = (const float*)d_in[5];
    const float* b3  = (const float*)d_in[6];
    const float* rw1 = (const float*)d_in[7];
    const float* rw2 = (const float*)d_in[8];
    const float* fcw = (const float*)d_in[9];
    const float* fcb = (const float*)d_in[10];
    float* out = (float*)d_out;

    conv1_k<<<2048, 256>>>(x, w1, b1);
    conv2_k<<<512, 256>>>(w2, b2);
    conv3_k<<<512, 256>>>(w3, b3);
    uhat1_k<<<512, 256>>>(rw1);
    route1_k<<<1024, 256>>>();
    route2_k<<<512, 256>>>(rw2, fcw, fcb, out);
}

// round 2
// speedup vs baseline: 1.3929x; 1.3929x over previous
#include <cuda_runtime.h>
#include <math.h>

typedef unsigned long long u64;

__device__ __forceinline__ u64 pk2(float lo, float hi) {
    u64 r; asm("mov.b64 %0,{%1,%2};" : "=l"(r) : "f"(lo), "f"(hi)); return r;
}
__device__ __forceinline__ void fma2(u64& d, u64 a, u64 b) {
    asm("fma.rn.f32x2 %0,%1,%2,%0;" : "+l"(d) : "l"(a), "l"(b));
}
__device__ __forceinline__ float2 up2(u64 v) {
    float2 f; asm("mov.b64 {%0,%1},%2;" : "=f"(f.x), "=f"(f.y) : "l"(v)); return f;
}

// ---------------- scratch (device globals; no allocation) ----------------
__device__ float g_h1[512*8*32*32];      // conv1 pooled out [b][oc][32][32]
__device__ float g_h2[512*16*16*16];     // conv2 pooled out [b][oc][16][16]
__device__ float g_feats[512*64*32];     // feats [b][r=64][c=32]
__device__ float g_uhat[512*64*256];     // u_hat [b][r][no=n*8+o]
__device__ float g_v1[512*256];          // v1 [b][n=32][o=8]

// ---------------- conv1: [512,3,64,64] -> relu -> pool -> g_h1 ----------------
__global__ __launch_bounds__(256) void conv1_k(const float* __restrict__ x,
                                               const float* __restrict__ w,
                                               const float* __restrict__ bias) {
    __shared__ float2 ws2[216];
    __shared__ float bs[8];
    int tid = threadIdx.x;
    if (tid < 216) { float v = w[tid]; ws2[tid] = make_float2(v, v); }
    if (tid < 8)   bs[tid] = bias[tid];
    __syncthreads();

    int b   = blockIdx.x >> 2;
    int pos = ((blockIdx.x & 3) << 8) + tid;
    int ph = pos >> 5, pw_ = pos & 31;
    int y0 = 2*ph - 1, x0 = 2*pw_ - 1;

    float win[3][4][4];
#pragma unroll
    for (int c = 0; c < 3; c++) {
#pragma unroll
        for (int yy = 0; yy < 4; yy++) {
            int y = y0 + yy;
            bool yok = (y >= 0 && y < 64);
            const float* row = x + ((b*3 + c)*64 + y)*64;
#pragma unroll
            for (int xx = 0; xx < 4; xx++) {
                int xp = x0 + xx;
                win[c][yy][xx] = (yok && xp >= 0 && xp < 64) ? row[xp] : 0.f;
            }
        }
    }

    // packed vertical pairs: pw[c][ky][kx] = (win[ky][kx], win[ky+1][kx])
    u64 pwv[3][3][4];
#pragma unroll
    for (int c = 0; c < 3; c++)
#pragma unroll
        for (int ky = 0; ky < 3; ky++)
#pragma unroll
            for (int kx = 0; kx < 4; kx++)
                pwv[c][ky][kx] = pk2(win[c][ky][kx], win[c][ky+1][kx]);

    const u64* wsu = (const u64*)ws2;
#pragma unroll 1
    for (int oc = 0; oc < 8; oc++) {
        u64 P0 = 0ull, P1 = 0ull;  // (a00,a10), (a01,a11)
        const u64* wp = wsu + oc*27;
#pragma unroll
        for (int c = 0; c < 3; c++)
#pragma unroll
            for (int ky = 0; ky < 3; ky++)
#pragma unroll
                for (int kx = 0; kx < 3; kx++) {
                    u64 wd = wp[c*9 + ky*3 + kx];
                    fma2(P0, pwv[c][ky][kx],   wd);
                    fma2(P1, pwv[c][ky][kx+1], wd);
                }
        float2 p0 = up2(P0), p1 = up2(P1);
        float m = fmaxf(fmaxf(p0.x, p0.y), fmaxf(p1.x, p1.y)) + bs[oc];
        g_h1[((b*8 + oc)*32 + ph)*32 + pw_] = fmaxf(m, 0.f);
    }
}

// ---------------- conv2: g_h1 -> relu -> pool -> g_h2 ----------------
__global__ __launch_bounds__(256) void conv2_k(const float* __restrict__ w,
                                               const float* __restrict__ bias) {
    __shared__ float hs[8192];      // 8*32*32
    __shared__ float2 ws2[1152];    // 16*8*9, duplicated
    __shared__ float bs[16];
    int tid = threadIdx.x, b = blockIdx.x;
    for (int i = tid; i < 8192; i += 256) hs[i] = g_h1[b*8192 + i];
    for (int i = tid; i < 1152; i += 256) { float v = w[i]; ws2[i] = make_float2(v, v); }
    if (tid < 16) bs[tid] = bias[tid];
    __syncthreads();

    int ph = tid >> 4, pw_ = tid & 15;
    int y0 = 2*ph - 1, x0 = 2*pw_ - 1;

    u64 accP[16][2];
#pragma unroll
    for (int oc = 0; oc < 16; oc++) { accP[oc][0] = 0ull; accP[oc][1] = 0ull; }

    const u64* wsu = (const u64*)ws2;
#pragma unroll 1
    for (int ic = 0; ic < 8; ic++) {
        float win[4][4];
#pragma unroll
        for (int yy = 0; yy < 4; yy++) {
            int y = y0 + yy;
            bool yok = (y >= 0 && y < 32);
#pragma unroll
            for (int xx = 0; xx < 4; xx++) {
                int xp = x0 + xx;
                win[yy][xx] = (yok && xp >= 0 && xp < 32) ? hs[ic*1024 + y*32 + xp] : 0.f;
            }
        }
        u64 pwv[3][4];
#pragma unroll
        for (int ky = 0; ky < 3; ky++)
#pragma unroll
            for (int kx = 0; kx < 4; kx++)
                pwv[ky][kx] = pk2(win[ky][kx], win[ky+1][kx]);

#pragma unroll
        for (int oc = 0; oc < 16; oc++) {
            const u64* wp = wsu + (oc*8 + ic)*9;
#pragma unroll
            for (int ky = 0; ky < 3; ky++)
#pragma unroll
                for (int kx = 0; kx < 3; kx++) {
                    u64 wd = wp[ky*3 + kx];
                    fma2(accP[oc][0], pwv[ky][kx],   wd);
                    fma2(accP[oc][1], pwv[ky][kx+1], wd);
                }
        }
    }
#pragma unroll
    for (int oc = 0; oc < 16; oc++) {
        float2 p0 = up2(accP[oc][0]), p1 = up2(accP[oc][1]);
        float m = fmaxf(fmaxf(p0.x, p0.y), fmaxf(p1.x, p1.y)) + bs[oc];
        g_h2[((b*16 + oc)*16 + ph)*16 + pw_] = fmaxf(m, 0.f);
    }
}

// ---------------- conv3: g_h2 -> relu -> pool -> g_feats[b][r][c] ----------------
__global__ __launch_bounds__(256) void conv3_k(const float* __restrict__ w,
                                               const float* __restrict__ bias) {
    __shared__ float2 ws2[4608];    // 32*16*9 duplicated (36864 B)
    __shared__ float hs[2048];      // half the ic planes (8192 B)
    __shared__ float bs[32];
    int tid = threadIdx.x, b = blockIdx.x;
    for (int i = tid; i < 4608; i += 256) { float v = w[i]; ws2[i] = make_float2(v, v); }
    if (tid < 32) bs[tid] = bias[tid];

    int pos = tid & 63;
    int ocg = tid >> 6;
    int ph = pos >> 3, pw_ = pos & 7;
    int y0 = 2*ph - 1, x0 = 2*pw_ - 1;

    u64 accP[8][2];
#pragma unroll
    for (int j = 0; j < 8; j++) { accP[j][0] = 0ull; accP[j][1] = 0ull; }

    const u64* wsu = (const u64*)ws2;
#pragma unroll 1
    for (int p = 0; p < 2; p++) {
        __syncthreads();
        for (int i = tid; i < 2048; i += 256) hs[i] = g_h2[b*4096 + p*2048 + i];
        __syncthreads();

#pragma unroll 1
        for (int icl = 0; icl < 8; icl++) {
            float win[4][4];
#pragma unroll
            for (int yy = 0; yy < 4; yy++) {
                int y = y0 + yy;
                bool yok = (y >= 0 && y < 16);
#pragma unroll
                for (int xx = 0; xx < 4; xx++) {
                    int xp = x0 + xx;
                    win[yy][xx] = (yok && xp >= 0 && xp < 16) ? hs[icl*256 + y*16 + xp] : 0.f;
                }
            }
            u64 pwv[3][4];
#pragma unroll
            for (int ky = 0; ky < 3; ky++)
#pragma unroll
                for (int kx = 0; kx < 4; kx++)
                    pwv[ky][kx] = pk2(win[ky][kx], win[ky+1][kx]);

#pragma unroll
            for (int j = 0; j < 8; j++) {
                const u64* wp = wsu + ((ocg*8 + j)*16 + p*8 + icl)*9;
#pragma unroll
                for (int ky = 0; ky < 3; ky++)
#pragma unroll
                    for (int kx = 0; kx < 3; kx++) {
                        u64 wd = wp[ky*3 + kx];
                        fma2(accP[j][0], pwv[ky][kx],   wd);
                        fma2(accP[j][1], pwv[ky][kx+1], wd);
                    }
            }
        }
    }
#pragma unroll
    for (int j = 0; j < 8; j++) {
        float2 p0 = up2(accP[j][0]), p1 = up2(accP[j][1]);
        float m = fmaxf(fmaxf(p0.x, p0.y), fmaxf(p1.x, p1.y)) + bs[ocg*8 + j];
        g_feats[(b*64 + pos)*32 + ocg*8 + j] = fmaxf(m, 0.f);
    }
}

// ---------------- u_hat1: per-(r, 32-b tile) packed GEMM ----------------
// Wr layout (float2 units): [c]*132 + [k4]*33 + [l] ; entry = rw1 row (n=l,r),
// float pair (c*8+2k4, c*8+2k4+1)  -> output no = l*8 + 2k4 (+1)
__global__ __launch_bounds__(256) void uhat1_k(const float* __restrict__ rw1) {
    __shared__ float2 Wr[4224];     // 33792 B
    __shared__ float2 fe2[1024];    // [b_local=32][c=32] duplicated, 8192 B
    int tid = threadIdx.x;
    int r     = blockIdx.x >> 4;
    int bbase = (blockIdx.x & 15) * 32;

#pragma unroll
    for (int ch = 0; ch < 16; ch++) {
        int i = tid + ch*256;
        int l = i >> 7, j = i & 127;
        float2 v = ((const float2*)(rw1 + (l*64 + r)*256))[j];
        int c = j >> 2, k4 = j & 3;
        Wr[c*132 + k4*33 + l] = v;
    }
#pragma unroll
    for (int k = 0; k < 4; k++) {
        int i = tid + k*256;
        int bb = i >> 5, c = i & 31;
        float v = g_feats[((bbase + bb)*64 + r)*32 + c];
        fe2[bb*32 + c] = make_float2(v, v);
    }
    __syncthreads();

    int wd = tid >> 5, l = tid & 31;   // warp -> 4-b group; lane -> n = l
    const u64* WrU = (const u64*)Wr;
    const u64* feU = (const u64*)fe2;

    u64 acc[4][4];
#pragma unroll
    for (int j = 0; j < 4; j++)
#pragma unroll
        for (int k4 = 0; k4 < 4; k4++) acc[j][k4] = 0ull;

#pragma unroll 4
    for (int c = 0; c < 32; c++) {
        u64 f[4], wv[4];
#pragma unroll
        for (int j = 0; j < 4; j++) f[j] = feU[(wd*4 + j)*32 + c];
#pragma unroll
        for (int k4 = 0; k4 < 4; k4++) wv[k4] = WrU[c*132 + k4*33 + l];
#pragma unroll
        for (int j = 0; j < 4; j++)
#pragma unroll
            for (int k4 = 0; k4 < 4; k4++) fma2(acc[j][k4], f[j], wv[k4]);
    }

#pragma unroll
    for (int j = 0; j < 4; j++) {
        float2 p0 = up2(acc[j][0]), p1 = up2(acc[j][1]);
        float2 p2 = up2(acc[j][2]), p3 = up2(acc[j][3]);
        float4* dst = (float4*)(g_uhat + ((bbase + wd*4 + j)*64 + r)*256 + l*8);
        dst[0] = make_float4(p0.x, p0.y, p1.x, p1.y);
        dst[1] = make_float4(p2.x, p2.y, p3.x, p3.y);
    }
}

// ---------------- routing1: block per (b, 16-n half), warp per n ----------------
__global__ __launch_bounds__(512) void route1_k() {
    __shared__ float uh[64*129];    // [r][no_local 128], stride 129
    __shared__ float cc_s[16*64];
    __shared__ float vv_s[16*8];
    int tid = threadIdx.x;
    int w = tid >> 5, lane = tid & 31;
    int b  = blockIdx.x >> 1;
    int ng = blockIdx.x & 1;
    const float* src = g_uhat + b*16384 + ng*128;

#pragma unroll
    for (int k = 0; k < 16; k++) {
        int i = tid + k*512;
        int r = i >> 7, j = i & 127;
        uh[r*129 + j] = src[r*256 + j];
    }
    __syncthreads();

    float b0 = 0.f, b1 = 0.f;   // bij for (n=w, r=lane) and (n=w, r=lane+32)
    for (int it = 0; it < 3; it++) {
        float c0, c1;
        if (it == 0) {
            c0 = c1 = 1.f/64.f;
        } else {
            float m = fmaxf(b0, b1);
#pragma unroll
            for (int off = 16; off; off >>= 1) m = fmaxf(m, __shfl_xor_sync(0xffffffffu, m, off));
            float e0 = expf(b0 - m), e1 = expf(b1 - m);
            float s = e0 + e1;
#pragma unroll
            for (int off = 16; off; off >>= 1) s += __shfl_xor_sync(0xffffffffu, s, off);
            float inv = 1.f/s;
            c0 = e0*inv; c1 = e1*inv;
        }
        cc_s[w*64 + lane]      = c0;
        cc_s[w*64 + lane + 32] = c1;
        __syncwarp();

        // s_j: lane = (g=lane>>3, o=lane&7), partial over 16 r each
        int o = lane & 7, g = lane >> 3;
        float a = 0.f;
#pragma unroll 4
        for (int rr = 0; rr < 16; rr++) {
            int r = g*16 + rr;
            a += cc_s[w*64 + r] * uh[r*129 + w*8 + o];
        }
        a += __shfl_down_sync(0xffffffffu, a, 16);
        a += __shfl_down_sync(0xffffffffu, a, 8);

        if (lane < 8) {         // lanes 0..7 hold s[o]
            float n2 = a*a;
            n2 += __shfl_xor_sync(0x000000ffu, n2, 1);
            n2 += __shfl_xor_sync(0x000000ffu, n2, 2);
            n2 += __shfl_xor_sync(0x000000ffu, n2, 4);
            float scale = n2/((1.f + n2)*sqrtf(n2 + 1e-9f));
            vv_s[w*8 + lane] = scale*a;
        }
        __syncwarp();

        if (it < 2) {
            float d0 = 0.f, d1 = 0.f;
#pragma unroll
            for (int o2 = 0; o2 < 8; o2++) {
                float v = vv_s[w*8 + o2];
                d0 += uh[lane*129 + w*8 + o2]*v;
                d1 += uh[(lane + 32)*129 + w*8 + o2]*v;
            }
            b0 += d0; b1 += d1;
            __syncwarp();
        }
    }
    if (lane < 8) g_v1[b*256 + ng*128 + w*8 + lane] = vv_s[w*8 + lane];
}

// ---------------- routing2 + FC: block per 2 b, warp per n, u2 in registers ----------------
__global__ __launch_bounds__(512) void route2_k(const float* __restrict__ rw2,
                                                const float* __restrict__ fcw,
                                                const float* __restrict__ fcb,
                                                float* __restrict__ out) {
    __shared__ float fe_s[512];     // v1 for 2 batches
    __shared__ float vv2[480];      // v2 for 2 batches [t][n*16+o]
    int tid = threadIdx.x, w = tid >> 5, lane = tid & 31;
    int b0 = blockIdx.x * 2;
    fe_s[tid] = g_v1[b0*256 + tid];
    __syncthreads();

    if (w < 15) {
        float ua[16], ub[16];
#pragma unroll
        for (int o = 0; o < 16; o++) { ua[o] = 0.f; ub[o] = 0.f; }
        const float4* wp = (const float4*)(rw2 + (w*32 + lane)*128);
#pragma unroll
        for (int c = 0; c < 8; c++) {
            float fa = fe_s[lane*8 + c], fb = fe_s[256 + lane*8 + c];
#pragma unroll
            for (int q = 0; q < 4; q++) {
                float4 wv = wp[c*4 + q];
                ua[q*4+0] += fa*wv.x; ua[q*4+1] += fa*wv.y; ua[q*4+2] += fa*wv.z; ua[q*4+3] += fa*wv.w;
                ub[q*4+0] += fb*wv.x; ub[q*4+1] += fb*wv.y; ub[q*4+2] += fb*wv.z; ub[q*4+3] += fb*wv.w;
            }
        }

        float bij0 = 0.f, bij1 = 0.f;
        for (int it = 0; it < 3; it++) {
            float c0, c1;
            if (it == 0) {
                c0 = c1 = 1.f/32.f;
            } else {
                float m0 = bij0, m1 = bij1;
#pragma unroll
                for (int off = 16; off; off >>= 1) {
                    m0 = fmaxf(m0, __shfl_xor_sync(0xffffffffu, m0, off));
                    m1 = fmaxf(m1, __shfl_xor_sync(0xffffffffu, m1, off));
                }
                float e0 = expf(bij0 - m0), e1 = expf(bij1 - m1);
                float s0 = e0, s1 = e1;
#pragma unroll
                for (int off = 16; off; off >>= 1) {
                    s0 += __shfl_xor_sync(0xffffffffu, s0, off);
                    s1 += __shfl_xor_sync(0xffffffffu, s1, off);
                }
                c0 = e0/s0; c1 = e1/s1;
            }
            float sa[16], sb[16];
#pragma unroll
            for (int o = 0; o < 16; o++) { sa[o] = c0*ua[o]; sb[o] = c1*ub[o]; }
#pragma unroll
            for (int off = 16; off; off >>= 1) {
#pragma unroll
                for (int o = 0; o < 16; o++) {
                    sa[o] += __shfl_xor_sync(0xffffffffu, sa[o], off);
                    sb[o] += __shfl_xor_sync(0xffffffffu, sb[o], off);
                }
            }
            float na = 0.f, nb = 0.f;
#pragma unroll
            for (int o = 0; o < 16; o++) { na += sa[o]*sa[o]; nb += sb[o]*sb[o]; }
            float sca = na/((1.f + na)*sqrtf(na + 1e-9f));
            float scb = nb/((1.f + nb)*sqrtf(nb + 1e-9f));
#pragma unroll
            for (int o = 0; o < 16; o++) { sa[o] *= sca; sb[o] *= scb; }

            if (it < 2) {
                float d0 = 0.f, d1 = 0.f;
#pragma unroll
                for (int o = 0; o < 16; o++) { d0 += ua[o]*sa[o]; d1 += ub[o]*sb[o]; }
                bij0 += d0; bij1 += d1;
            } else if (lane == 0) {
#pragma unroll
                for (int o = 0; o < 16; o++) {
                    vv2[w*16 + o]       = sa[o];
                    vv2[240 + w*16 + o] = sb[o];
                }
            }
        }
    }
    __syncthreads();

    if (w < 15) {
        float a0 = 0.f, a1 = 0.f;
        for (int j = lane; j < 240; j += 32) {
            float wv = fcw[w*240 + j];
            a0 += vv2[j]*wv;
            a1 += vv2[240 + j]*wv;
        }
#pragma unroll
        for (int off = 16; off; off >>= 1) {
            a0 += __shfl_xor_sync(0xffffffffu, a0, off);
            a1 += __shfl_xor_sync(0xffffffffu, a1, off);
        }
        if (lane == 0) {
            float bb = fcb[w];
            out[b0*15 + w]       = a0 + bb;
            out[(b0 + 1)*15 + w] = a1 + bb;
        }
    }
}

// ---------------- launch ----------------
extern "C" void kernel_launch(void* const* d_in, const int* in_sizes, int n_in,
                              void* d_out, int out_size) {
    const float* x   = (const float*)d_in[0];
    const float* w1  = (const float*)d_in[1];
    const float* b1  = (const float*)d_in[2];
    const float* w2  = (const float*)d_in[3];
    const float* b2  = (const float*)d_in[4];
    const float* w3  = (const float*)d_in[5];
    const float* b3  = (const float*)d_in[6];
    const float* rw1 = (const float*)d_in[7];
    const float* rw2 = (const float*)d_in[8];
    const float* fcw = (const float*)d_in[9];
    const float* fcb = (const float*)d_in[10];
    float* out = (float*)d_out;

    conv1_k<<<2048, 256>>>(x, w1, b1);
    conv2_k<<<512, 256>>>(w2, b2);
    conv3_k<<<512, 256>>>(w3, b3);
    uhat1_k<<<1024, 256>>>(rw1);
    route1_k<<<1024, 512>>>();
    route2_k<<<256, 512>>>(rw2, fcw, fcb, out);
}